// round 6
// baseline (speedup 1.0000x reference)
#include <cuda_runtime.h>

#define B_  16
#define N_  4096
#define D_  1024
#define K_  2048

#define TOK_ 32          // tokens per fused block
#define BLKS_PER_B_ (N_ / TOK_)   // 128

typedef unsigned long long ull;

__device__ int   g_rank[B_ * N_];
__device__ float g_partial[B_ * BLKS_PER_B_ * D_];

__device__ __forceinline__ unsigned ord32(float v) {
    unsigned bits = __float_as_uint(v);
    return (bits & 0x80000000u) ? ~bits : (bits | 0x80000000u);
}

__device__ __forceinline__ void cswap(ull& x, ull& y, bool desc) {
    // descending: larger first
    const bool sw = desc ? (x < y) : (x > y);
    const ull a = sw ? y : x;
    const ull b = sw ? x : y;
    x = a; y = b;
}

// -------------------------------------------------------------------------
// Kernel A: per-batch bitonic sort -> exact descending rank.
// grid (B), block 1024, 32KB smem of u64 keys.
// key = (ord32(v) << 12) | (4095 - idx): descending u64 order reproduces
// jax.lax.top_k exactly (descending by value, ties by smaller index first).
// Register-blocked: each thread owns the 4-element group
// {a, a+j/2, a+j, a+j+j/2} and runs TWO stages per __syncthreads (the
// direction bit a&k is uniform over the group because k >= 2j). Odd tail
// (j=1) is 2 contiguous pairs per thread. 42 barrier rounds vs 78.
// -------------------------------------------------------------------------
__global__ void __launch_bounds__(1024)
sort_rank_kernel(const float* __restrict__ attn) {
    __shared__ ull sk[N_];
    const int b = blockIdx.x;
    const int t = threadIdx.x;

    #pragma unroll
    for (int p = 0; p < N_ / 1024; p++) {
        const int i = p * 1024 + t;
        sk[i] = ((ull)ord32(attn[b * N_ + i]) << 12) | (unsigned)(4095 - i);
    }
    __syncthreads();

    #pragma unroll 1
    for (int k = 2; k <= N_; k <<= 1) {
        int j = k >> 1;
        #pragma unroll 1
        while (j >= 2) {
            const int j2 = j >> 1;
            const int s  = __popc(j2 - 1);               // log2(j2)
            const int a  = (t & (j2 - 1)) | ((t >> s) << (s + 2));
            ull e0 = sk[a];
            ull e1 = sk[a + j2];
            ull e2 = sk[a + j];
            ull e3 = sk[a + j + j2];
            const bool desc = ((a & k) == 0);
            // stage j: (e0,e2), (e1,e3)
            cswap(e0, e2, desc);
            cswap(e1, e3, desc);
            // stage j/2: (e0,e1), (e2,e3)
            cswap(e0, e1, desc);
            cswap(e2, e3, desc);
            sk[a]          = e0;
            sk[a + j2]     = e1;
            sk[a + j]      = e2;
            sk[a + j + j2] = e3;
            __syncthreads();
            j >>= 2;
        }
        if (j == 1) {
            // single stage j=1: 2 contiguous pairs per thread
            const int a = 4 * t;
            ull e0 = sk[a], e1 = sk[a + 1], e2 = sk[a + 2], e3 = sk[a + 3];
            cswap(e0, e1, (a & k) == 0);
            cswap(e2, e3, ((a + 2) & k) == 0);
            sk[a] = e0; sk[a + 1] = e1; sk[a + 2] = e2; sk[a + 3] = e3;
            __syncthreads();
        }
    }

    #pragma unroll
    for (int p = 0; p < N_ / 1024; p++) {
        const int pos = p * 1024 + t;
        const int idx = 4095 - (int)(sk[pos] & 0xFFFu);
        g_rank[b * N_ + idx] = pos;
    }
}

// -------------------------------------------------------------------------
// Kernel B: fused gather + pruned-sum. grid (BLKS_PER_B, B), block 256.
// Streams TOK_ consecutive token rows (sequential 128KB read per block).
// Per-token branch is uniform across the block (no divergence):
//   rank < K : write row to out[b, rank, :]
//   else     : accumulate into per-thread float4 partial
// -------------------------------------------------------------------------
__global__ void __launch_bounds__(256)
fused_kernel(const float* __restrict__ seq, float* __restrict__ out) {
    const int b   = blockIdx.y;
    const int blk = blockIdx.x;
    const int t   = threadIdx.x;
    const int n0  = blk * TOK_;

    const float4* __restrict__ src =
        reinterpret_cast<const float4*>(seq + ((size_t)(b * N_ + n0)) * D_);
    const int* __restrict__ rnk = g_rank + b * N_ + n0;

    float4 acc = make_float4(0.f, 0.f, 0.f, 0.f);

    #pragma unroll 8
    for (int k = 0; k < TOK_; k++) {
        const float4 v = src[k * (D_ / 4) + t];
        const int r = rnk[k];
        if (r < K_) {
            reinterpret_cast<float4*>(
                out + ((size_t)(b * (K_ + 1) + r)) * D_)[t] = v;
        } else {
            acc.x += v.x; acc.y += v.y; acc.z += v.z; acc.w += v.w;
        }
    }

    reinterpret_cast<float4*>(g_partial)
        [((size_t)b * BLKS_PER_B_ + blk) * (D_ / 4) + t] = acc;
}

// -------------------------------------------------------------------------
// Kernel C: reduce partials, write mixup row out[b, K, :].
// grid (B, 16), block 256. rem_cnt = 2048 + 1e-10 == 2048.0f in fp32.
// -------------------------------------------------------------------------
__global__ void __launch_bounds__(256)
rem_kernel(float* __restrict__ out) {
    const int b  = blockIdx.x;
    const int g  = threadIdx.x & 15;
    const int s  = threadIdx.x >> 4;
    const int c4 = blockIdx.y * 16 + g;

    const float4* __restrict__ p =
        reinterpret_cast<const float4*>(g_partial) +
        (size_t)b * BLKS_PER_B_ * (D_ / 4) + c4;

    float4 a = make_float4(0.f, 0.f, 0.f, 0.f);
    #pragma unroll
    for (int m = 0; m < 8; m++) {
        const float4 v = p[(size_t)(s + 16 * m) * (D_ / 4)];
        a.x += v.x; a.y += v.y; a.z += v.z; a.w += v.w;
    }

    __shared__ float4 red[16][16];
    red[s][g] = a;
    __syncthreads();

    #pragma unroll
    for (int step = 8; step >= 1; step >>= 1) {
        if (s < step) {
            float4 o = red[s + step][g];
            red[s][g].x += o.x; red[s][g].y += o.y;
            red[s][g].z += o.z; red[s][g].w += o.w;
        }
        __syncthreads();
    }

    if (s == 0) {
        const float sc = 0.05f / 2048.0f;
        float4 r = red[0][g];
        r.x *= sc; r.y *= sc; r.z *= sc; r.w *= sc;
        reinterpret_cast<float4*>(
            out + ((size_t)(b * (K_ + 1) + K_)) * D_)[c4] = r;
    }
}

extern "C" void kernel_launch(void* const* d_in, const int* in_sizes, int n_in,
                              void* d_out, int out_size) {
    const float* seq  = (const float*)d_in[0];   // (16, 4096, 1024) fp32
    const float* attn = (const float*)d_in[1];   // (16, 4096) fp32
    float* out = (float*)d_out;                  // (16, 2049, 1024) fp32
    (void)in_sizes; (void)n_in; (void)out_size;

    sort_rank_kernel<<<B_, 1024>>>(attn);
    fused_kernel    <<<dim3(BLKS_PER_B_, B_), 256>>>(seq, out);
    rem_kernel      <<<dim3(B_, 16), 256>>>(out);
}